// round 7
// baseline (speedup 1.0000x reference)
#include <cuda_runtime.h>
#include <cstdint>
#include <cstddef>

// Problem constants
#define Bc   256
#define HIDc 512
#define Hc   8
#define Dc   64
#define FFc  2048
#define Lc   6

#define EPS_ATTN 1e-6f
#define EPS_LN   1e-5f

// ---------------- scratch (device globals; no allocations allowed) ----------
__device__ float g_h[Bc * HIDc];
__device__ float g_q[Bc * HIDc];
__device__ float g_k[Bc * HIDc];
__device__ float g_v[Bc * HIDc];
__device__ float g_attn[Bc * HIDc];
__device__ float g_ff[Bc * FFc];
__device__ float g_part[4 * Bc * HIDc];   // split-K partials for O / FF2

// ---------------- embedding + positional encoding ---------------------------
__global__ __launch_bounds__(256) void embed_kernel(
    const int* __restrict__ x, const int* __restrict__ pos_p,
    const float* __restrict__ emb, float* __restrict__ h)
{
    int i = blockIdx.x * 256 + threadIdx.x;           // 0 .. B*HID-1
    int b = i >> 9;
    int c = i & 511;
    float posf = (float)(*pos_p);
    int j2 = c & ~1;                                   // 2*j
    float e = (float)j2 * (1.0f / (float)HIDc);
    float ang = posf * powf(10000.0f, -e);
    float pe = (c & 1) ? cosf(ang) : sinf(ang);
    h[i] = emb[(size_t)x[b] * HIDc + c] + pe;
}

// ---------------- generic tiled fp32 GEMM body -------------------------------
// C[M,N] (+)= A[M,K] @ W[K,N]; A,W row-major.  act: 0 none, 1 elu+1, 2 relu.
template<int BM, int BN, int BK, int TM, int TN>
__device__ __forceinline__ void gemm_body(
    const float* __restrict__ A, const float* __restrict__ W,
    const float* __restrict__ bias, float* __restrict__ C,
    int N, int K, int k0, int kLen, int act)
{
    constexpr int NT = (BM / TM) * (BN / TN);          // threads per block
    __shared__ float As[BK][BM + 1];                   // +1 pad: conflict-free
    __shared__ float Ws[BK][BN];

    const int tid = threadIdx.x;
    const int tx  = tid % (BN / TN);
    const int ty  = tid / (BN / TN);
    const int row0 = blockIdx.y * BM;
    const int col0 = blockIdx.x * BN;

    float acc[TM][TN];
#pragma unroll
    for (int i = 0; i < TM; i++)
#pragma unroll
        for (int j = 0; j < TN; j++) acc[i][j] = 0.0f;

    for (int kt = k0; kt < k0 + kLen; kt += BK) {
        // load A tile (BK x BM): consecutive tids read consecutive k (64B runs)
#pragma unroll
        for (int idx = tid; idx < BK * BM; idx += NT) {
            int kk = idx % BK, mm = idx / BK;
            As[kk][mm] = A[(size_t)(row0 + mm) * K + kt + kk];
        }
        // load W tile (BK x BN): fully coalesced
#pragma unroll
        for (int idx = tid; idx < BK * BN; idx += NT) {
            int nn = idx % BN, kk = idx / BN;
            Ws[kk][nn] = W[(size_t)(kt + kk) * N + col0 + nn];
        }
        __syncthreads();

#pragma unroll
        for (int kk = 0; kk < BK; kk++) {
            float a[TM], w[TN];
#pragma unroll
            for (int i = 0; i < TM; i++) a[i] = As[kk][ty * TM + i];
#pragma unroll
            for (int j = 0; j < TN; j++) w[j] = Ws[kk][tx * TN + j];
#pragma unroll
            for (int i = 0; i < TM; i++)
#pragma unroll
                for (int j = 0; j < TN; j++)
                    acc[i][j] = fmaf(a[i], w[j], acc[i][j]);
        }
        __syncthreads();
    }

#pragma unroll
    for (int i = 0; i < TM; i++) {
        int row = row0 + ty * TM + i;
#pragma unroll
        for (int j = 0; j < TN; j++) {
            int col = col0 + tx * TN + j;
            float vv = acc[i][j];
            if (bias) vv += bias[col];
            if (act == 1) vv = (vv > 0.0f) ? (vv + 1.0f) : expf(vv);   // elu(x)+1
            else if (act == 2) vv = fmaxf(vv, 0.0f);                   // relu
            C[(size_t)row * N + col] = vv;
        }
    }
}

// Generic GEMM; grid.z = split-K count; each split writes its own partial slab.
__global__ __launch_bounds__(256) void gemm_kernel(
    const float* __restrict__ A, const float* __restrict__ W,
    const float* __restrict__ bias, float* __restrict__ C,
    int M, int N, int K, int act)
{
    int kLen = K / gridDim.z;
    int k0   = blockIdx.z * kLen;
    C += (size_t)blockIdx.z * M * N;
    gemm_body<64, 64, 16, 4, 4>(A, W, bias, C, N, K, k0, kLen, act);
}

// Fused QKV GEMM: grid.z selects {Q,K,V}. Q,K get elu+1 epilogue.
__global__ __launch_bounds__(256) void gemm_qkv_kernel(
    const float* __restrict__ A,
    const float* __restrict__ Wq, const float* __restrict__ Wk, const float* __restrict__ Wv,
    const float* __restrict__ bq, const float* __restrict__ bk, const float* __restrict__ bv,
    float* __restrict__ Cq, float* __restrict__ Ck, float* __restrict__ Cv)
{
    const float* W; const float* bias; float* C; int act;
    if (blockIdx.z == 0)      { W = Wq; bias = bq; C = Cq; act = 1; }
    else if (blockIdx.z == 1) { W = Wk; bias = bk; C = Ck; act = 1; }
    else                      { W = Wv; bias = bv; C = Cv; act = 0; }
    gemm_body<64, 64, 16, 4, 4>(A, W, bias, C, HIDc, HIDc, 0, HIDc, act);
}

// ---------------- fused linear-attention state update ------------------------
// One block per (b,h). Streams S once: S_out = S + k v^T, num = q . S_out,
// den = q . (Z + k) + eps, attn = num/den.  Fully coalesced (4KB rows).
__global__ __launch_bounds__(256) void attn_state_kernel(
    const float* __restrict__ S_in, const float* __restrict__ Z_in,
    const float* __restrict__ q, const float* __restrict__ k,
    const float* __restrict__ v,
    float* __restrict__ S_out, float* __restrict__ Z_out,
    float* __restrict__ attn)
{
    int bh = blockIdx.x;                 // 0 .. B*H-1
    int t  = threadIdx.x;                // 256 threads
    __shared__ float qs[Dc], ks[Dc], vs[Dc];
    __shared__ float red[256];
    __shared__ float s_den;

    int voff = bh * Dc;                  // == b*HID + h*D
    if (t < Dc) {
        float qq = q[voff + t];
        float kk = k[voff + t];
        qs[t] = qq; ks[t] = kk; vs[t] = v[voff + t];
        float zn = Z_in[voff + t] + kk;
        Z_out[voff + t] = zn;
        red[t] = qq * zn;
    }
    __syncthreads();
    if (t == 0) {
        float s = 0.0f;
#pragma unroll
        for (int i = 0; i < Dc; i++) s += red[i];
        s_den = s + EPS_ATTN;
    }
    __syncthreads();

    int m  = t & 63;
    int d0 = t >> 6;                     // 0..3
    size_t base = (size_t)bh * (Dc * Dc);
    float pnum = 0.0f;
#pragma unroll
    for (int i = 0; i < 16; i++) {
        int d = 4 * i + d0;
        size_t idx = base + (size_t)d * Dc + m;
        float s  = S_in[idx];
        float sn = fmaf(ks[d], vs[m], s);
        S_out[idx] = sn;
        pnum = fmaf(qs[d], sn, pnum);
    }
    red[t] = pnum;
    __syncthreads();
    if (t < Dc) {
        float num = red[t] + red[t + 64] + red[t + 128] + red[t + 192];
        attn[voff + t] = num / s_den;
    }
}

// ---------------- LayerNorm (fuses split-K reduce + bias + residual) ---------
// x = sum_p parts[p] + bias + res ; out = (x-mean)/sqrt(var+eps)*g + b
__global__ __launch_bounds__(256) void ln_kernel(
    const float* __restrict__ parts, int nparts, int partStride,
    const float* __restrict__ bias, const float* __restrict__ res,
    const float* __restrict__ g, const float* __restrict__ b,
    float* __restrict__ out)
{
    int row = blockIdx.x;                // 0..B-1
    int t   = threadIdx.x;               // 256 threads, 2 elems each
    float vv[2];
#pragma unroll
    for (int r = 0; r < 2; r++) {
        int c = t + 256 * r;
        size_t idx = (size_t)row * HIDc + c;
        float x = 0.0f;
        for (int p = 0; p < nparts; p++) x += parts[(size_t)p * partStride + idx];
        if (bias) x += bias[c];
        if (res)  x += res[idx];
        vv[r] = x;
    }
    float s = vv[0] + vv[1];
    float qsum = vv[0] * vv[0] + vv[1] * vv[1];
#pragma unroll
    for (int o = 16; o > 0; o >>= 1) {
        s    += __shfl_down_sync(0xffffffffu, s, o);
        qsum += __shfl_down_sync(0xffffffffu, qsum, o);
    }
    __shared__ float ss[8], sq[8];
    __shared__ float s_mean, s_rstd;
    int warp = t >> 5, lane = t & 31;
    if (lane == 0) { ss[warp] = s; sq[warp] = qsum; }
    __syncthreads();
    if (t == 0) {
        float S = 0.0f, Q = 0.0f;
#pragma unroll
        for (int w = 0; w < 8; w++) { S += ss[w]; Q += sq[w]; }
        float mean = S * (1.0f / (float)HIDc);
        float var  = Q * (1.0f / (float)HIDc) - mean * mean;
        s_mean = mean;
        s_rstd = rsqrtf(var + EPS_LN);
    }
    __syncthreads();
#pragma unroll
    for (int r = 0; r < 2; r++) {
        int c = t + 256 * r;
        size_t idx = (size_t)row * HIDc + c;
        out[idx] = (vv[r] - s_mean) * s_rstd * g[c] + b[c];
    }
}

// ---------------- launcher ----------------------------------------------------
extern "C" void kernel_launch(void* const* d_in, const int* in_sizes, int n_in,
                              void* d_out, int out_size)
{
    (void)in_sizes; (void)n_in; (void)out_size;

    const int*   x     = (const int*)  d_in[0];
    const int*   pos   = (const int*)  d_in[1];
    const float* S     = (const float*)d_in[2];
    const float* Z     = (const float*)d_in[3];
    const float* emb   = (const float*)d_in[4];
    const float* Wq    = (const float*)d_in[5];
    const float* bq    = (const float*)d_in[6];
    const float* Wk    = (const float*)d_in[7];
    const float* bk    = (const float*)d_in[8];
    const float* Wv    = (const float*)d_in[9];
    const float* bv    = (const float*)d_in[10];
    const float* Wo    = (const float*)d_in[11];
    const float* bo    = (const float*)d_in[12];
    const float* W1    = (const float*)d_in[13];
    const float* b1    = (const float*)d_in[14];
    const float* W2    = (const float*)d_in[15];
    const float* b2    = (const float*)d_in[16];
    const float* ln1_g = (const float*)d_in[17];
    const float* ln1_b = (const float*)d_in[18];
    const float* ln2_g = (const float*)d_in[19];
    const float* ln2_b = (const float*)d_in[20];
    const float* lnf_g = (const float*)d_in[21];
    const float* lnf_b = (const float*)d_in[22];

    float* h_buf;  cudaGetSymbolAddress((void**)&h_buf,  g_h);
    float* q_buf;  cudaGetSymbolAddress((void**)&q_buf,  g_q);
    float* k_buf;  cudaGetSymbolAddress((void**)&k_buf,  g_k);
    float* v_buf;  cudaGetSymbolAddress((void**)&v_buf,  g_v);
    float* a_buf;  cudaGetSymbolAddress((void**)&a_buf,  g_attn);
    float* ff_buf; cudaGetSymbolAddress((void**)&ff_buf, g_ff);
    float* p_buf;  cudaGetSymbolAddress((void**)&p_buf,  g_part);

    const size_t SZ = (size_t)Bc * Hc * Dc * Dc;  // 8388608 per layer
    const size_t ZZ = (size_t)Bc * Hc * Dc;       // 131072  per layer
    const size_t MN = (size_t)Bc * HIDc;          // 131072

    float* out   = (float*)d_out;
    float* out_h = out;                           // [B,HID]
    float* out_S = out + MN;                      // [L,B,H,D,D]
    float* out_Z = out + MN + (size_t)Lc * SZ;    // [L,B,H,D]

    // embedding + positional encoding
    embed_kernel<<<(Bc * HIDc) / 256, 256>>>(x, pos, emb, h_buf);

    for (int l = 0; l < Lc; l++) {
        const float* Wq_l = Wq + (size_t)l * HIDc * HIDc;
        const float* Wk_l = Wk + (size_t)l * HIDc * HIDc;
        const float* Wv_l = Wv + (size_t)l * HIDc * HIDc;
        const float* Wo_l = Wo + (size_t)l * HIDc * HIDc;
        const float* W1_l = W1 + (size_t)l * HIDc * FFc;
        const float* W2_l = W2 + (size_t)l * FFc * HIDc;

        // QKV: one launch, grid.z selects matrix (96 blocks)
        gemm_qkv_kernel<<<dim3(HIDc / 64, Bc / 64, 3), 256>>>(
            h_buf, Wq_l, Wk_l, Wv_l,
            bq + l * HIDc, bk + l * HIDc, bv + l * HIDc,
            q_buf, k_buf, v_buf);

        // fused S update / Z update / attention numerator+denominator
        attn_state_kernel<<<Bc * Hc, 256>>>(
            S + (size_t)l * SZ, Z + (size_t)l * ZZ,
            q_buf, k_buf, v_buf,
            out_S + (size_t)l * SZ, out_Z + (size_t)l * ZZ, a_buf);

        // O projection, split-K=4 into partials (bias folded into LN1)
        gemm_kernel<<<dim3(HIDc / 64, Bc / 64, 4), 256>>>(
            a_buf, Wo_l, nullptr, p_buf, Bc, HIDc, HIDc, 0);

        // h = LN1(h + attn@Wo + bo)
        ln_kernel<<<Bc, 256>>>(p_buf, 4, (int)MN, bo + l * HIDc, h_buf,
                               ln1_g + l * HIDc, ln1_b + l * HIDc, h_buf);

        // FF1 with fused ReLU (128 blocks, no split needed)
        gemm_kernel<<<dim3(FFc / 64, Bc / 64, 1), 256>>>(
            h_buf, W1_l, b1 + l * FFc, ff_buf, Bc, FFc, HIDc, 2);

        // FF2, split-K=4 into partials (bias folded into LN2)
        gemm_kernel<<<dim3(HIDc / 64, Bc / 64, 4), 256>>>(
            ff_buf, W2_l, nullptr, p_buf, Bc, HIDc, FFc, 0);

        // h = LN2(h + ff)
        ln_kernel<<<Bc, 256>>>(p_buf, 4, (int)MN, b2 + l * HIDc, h_buf,
                               ln2_g + l * HIDc, ln2_b + l * HIDc, h_buf);
    }

    // final LayerNorm straight into d_out
    ln_kernel<<<Bc, 256>>>(h_buf, 1, 0, nullptr, nullptr, lnf_g, lnf_b, out_h);
}

// round 8
// speedup vs baseline: 3.1745x; 3.1745x over previous
#include <cuda_runtime.h>
#include <cstdint>
#include <cstddef>

// Problem constants
#define Bc   256
#define HIDc 512
#define Hc   8
#define Dc   64
#define FFc  2048
#define Lc   6

#define EPS_ATTN 1e-6f
#define EPS_LN   1e-5f

#define MNc (Bc * HIDc)   // 131072

// ---------------- scratch (device globals; no allocations allowed) ----------
__device__ float g_h[MNc];
__device__ float g_attn[MNc];
__device__ float g_ff[Bc * FFc];
__device__ float g_part[8 * MNc];      // split-K partials for O / FF2 (8 slabs)
__device__ float g_qkvp[6 * MNc];      // QKV split-K=2 partials: [mat*2+split]

// ---------------- embedding + positional encoding ---------------------------
__global__ __launch_bounds__(256) void embed_kernel(
    const int* __restrict__ x, const int* __restrict__ pos_p,
    const float* __restrict__ emb, float* __restrict__ h)
{
    int i = blockIdx.x * 256 + threadIdx.x;           // 0 .. B*HID-1
    int b = i >> 9;
    int c = i & 511;
    float posf = (float)(*pos_p);
    int j2 = c & ~1;                                   // 2*j
    float e = (float)j2 * (1.0f / (float)HIDc);
    float ang = posf * powf(10000.0f, -e);
    float pe = (c & 1) ? cosf(ang) : sinf(ang);
    h[i] = emb[(size_t)x[b] * HIDc + c] + pe;
}

// ---------------- vectorized fp32 GEMM body ----------------------------------
// C[M,N] = A[M,K] @ W[K,N] over k in [k0, k0+kLen).
// 64x64 tile, BK=16, 256 threads, 4x4 microtile, float4 smem loads,
// register double-buffering of global tiles. act: 0 none, 2 relu.
__device__ __forceinline__ void gemm_body_v2(
    const float* __restrict__ A, const float* __restrict__ W,
    const float* __restrict__ bias, float* __restrict__ C,
    int N, int K, int k0, int kLen, int act)
{
    constexpr int BM = 64, BN = 64, BK = 16;
    constexpr int LDA = BM + 4;                    // 68: keeps 16B alignment
    __shared__ float As[BK * LDA];                 // k-major
    __shared__ float Ws[BK * BN];                  // k-major rows

    const int tid = threadIdx.x;
    const int tx  = tid & 15;                      // 0..15 -> N
    const int ty  = tid >> 4;                      // 0..15 -> M
    const int row0 = blockIdx.y * BM;
    const int col0 = blockIdx.x * BN;

    // global-load assignments (1 float4 per thread per tile, per operand)
    const int a_row = tid >> 2;                    // 0..63
    const int a_k   = (tid & 3) << 2;              // 0,4,8,12
    const int w_row = tid >> 4;                    // 0..15
    const int w_col = (tid & 15) << 2;             // 0..60

    const float* Aptr = A + (size_t)(row0 + a_row) * K + k0 + a_k;
    const float* Wptr = W + (size_t)(k0 + w_row) * N + col0 + w_col;

    float4 aR = *(const float4*)Aptr;
    float4 wR = *(const float4*)Wptr;

    float acc[4][4];
#pragma unroll
    for (int i = 0; i < 4; i++)
#pragma unroll
        for (int j = 0; j < 4; j++) acc[i][j] = 0.0f;

    const int ntiles = kLen / BK;
    for (int t = 0; t < ntiles; t++) {
        // commit prefetched tile to smem
        As[(a_k + 0) * LDA + a_row] = aR.x;
        As[(a_k + 1) * LDA + a_row] = aR.y;
        As[(a_k + 2) * LDA + a_row] = aR.z;
        As[(a_k + 3) * LDA + a_row] = aR.w;
        *(float4*)&Ws[w_row * BN + w_col] = wR;
        __syncthreads();

        if (t + 1 < ntiles) {                      // prefetch next tile
            aR = *(const float4*)(Aptr + (t + 1) * BK);
            wR = *(const float4*)(Wptr + (size_t)(t + 1) * BK * N);
        }

#pragma unroll
        for (int kk = 0; kk < BK; kk++) {
            float4 a4 = *(const float4*)&As[kk * LDA + ty * 4];
            float4 w4 = *(const float4*)&Ws[kk * BN  + tx * 4];
            float a[4] = {a4.x, a4.y, a4.z, a4.w};
            float w[4] = {w4.x, w4.y, w4.z, w4.w};
#pragma unroll
            for (int i = 0; i < 4; i++)
#pragma unroll
                for (int j = 0; j < 4; j++)
                    acc[i][j] = fmaf(a[i], w[j], acc[i][j]);
        }
        __syncthreads();
    }

    // epilogue: float4 stores
#pragma unroll
    for (int i = 0; i < 4; i++) {
        int row = row0 + ty * 4 + i;
        int col = col0 + tx * 4;
        float4 r;
        float* rv = (float*)&r;
#pragma unroll
        for (int j = 0; j < 4; j++) {
            float vv = acc[i][j];
            if (bias) vv += bias[col + j];
            if (act == 2) vv = fmaxf(vv, 0.0f);
            rv[j] = vv;
        }
        *(float4*)&C[(size_t)row * N + col] = r;
    }
}

// Generic GEMM; grid.z = split-K count; split z writes partial slab z of C.
__global__ __launch_bounds__(256) void gemm_kernel(
    const float* __restrict__ A, const float* __restrict__ W,
    const float* __restrict__ bias, float* __restrict__ C,
    int M, int N, int K, int act)
{
    int kLen = K / gridDim.z;
    int k0   = blockIdx.z * kLen;
    C += (size_t)blockIdx.z * M * N;
    gemm_body_v2(A, W, bias, C, N, K, k0, kLen, act);
}

// QKV GEMM, split-K=2 per matrix: grid.z in 0..5, mat = z>>1, split = z&1.
// Writes raw partials (no bias/act) to g_qkvp[z]. Epilogue fused in attn_state.
__global__ __launch_bounds__(256) void gemm_qkv_kernel(
    const float* __restrict__ A,
    const float* __restrict__ Wq, const float* __restrict__ Wk,
    const float* __restrict__ Wv, float* __restrict__ qkvp)
{
    int mat   = blockIdx.z >> 1;
    int split = blockIdx.z & 1;
    const float* W = (mat == 0) ? Wq : (mat == 1) ? Wk : Wv;
    float* C = qkvp + (size_t)blockIdx.z * MNc;
    gemm_body_v2(A, W, nullptr, C, HIDc, HIDc, split * (HIDc / 2), HIDc / 2, 0);
}

// ---------------- fused linear-attention state update ------------------------
// One block per (b,h). Fuses: QKV split-K reduce + bias + elu(+1);
// S_out = S + k v^T, num = q . S_out, den = q.(Z+k)+eps, attn = num/den.
__global__ __launch_bounds__(256) void attn_state_kernel(
    const float* __restrict__ S_in, const float* __restrict__ Z_in,
    const float* __restrict__ qkvp,
    const float* __restrict__ bq, const float* __restrict__ bk,
    const float* __restrict__ bv,
    float* __restrict__ S_out, float* __restrict__ Z_out,
    float* __restrict__ attn)
{
    int bh = blockIdx.x;                 // 0 .. B*H-1
    int t  = threadIdx.x;                // 256 threads
    __shared__ float qs[Dc], ks[Dc], vs[Dc];
    __shared__ float red[256];
    __shared__ float s_den;

    int voff = bh * Dc;                  // == b*HID + h*D
    if (t < Dc) {
        int c = ((bh & (Hc - 1)) << 6) + t;          // column within HID
        float qq = qkvp[voff + t] + qkvp[MNc + voff + t] + bq[c];
        qq = (qq > 0.0f) ? (qq + 1.0f) : expf(qq);   // elu(x)+1
        float kk = qkvp[2 * MNc + voff + t] + qkvp[3 * MNc + voff + t] + bk[c];
        kk = (kk > 0.0f) ? (kk + 1.0f) : expf(kk);
        float vv = qkvp[4 * MNc + voff + t] + qkvp[5 * MNc + voff + t] + bv[c];
        qs[t] = qq; ks[t] = kk; vs[t] = vv;
        float zn = Z_in[voff + t] + kk;
        Z_out[voff + t] = zn;
        red[t] = qq * zn;
    }
    __syncthreads();
    if (t == 0) {
        float s = 0.0f;
#pragma unroll
        for (int i = 0; i < Dc; i++) s += red[i];
        s_den = s + EPS_ATTN;
    }
    __syncthreads();

    int m  = t & 63;
    int d0 = t >> 6;                     // 0..3
    size_t base = (size_t)bh * (Dc * Dc);
    float pnum = 0.0f;
#pragma unroll
    for (int i = 0; i < 16; i++) {
        int d = 4 * i + d0;
        size_t idx = base + (size_t)d * Dc + m;
        float s  = S_in[idx];
        float sn = fmaf(ks[d], vs[m], s);
        S_out[idx] = sn;
        pnum = fmaf(qs[d], sn, pnum);
    }
    red[t] = pnum;
    __syncthreads();
    if (t < Dc) {
        float num = red[t] + red[t + 64] + red[t + 128] + red[t + 192];
        attn[voff + t] = num / s_den;
    }
}

// ---------------- LayerNorm (fuses split-K reduce + bias + residual) ---------
__global__ __launch_bounds__(256) void ln_kernel(
    const float* __restrict__ parts, int nparts, int partStride,
    const float* __restrict__ bias, const float* __restrict__ res,
    const float* __restrict__ g, const float* __restrict__ b,
    float* __restrict__ out)
{
    int row = blockIdx.x;                // 0..B-1
    int t   = threadIdx.x;               // 256 threads, 2 elems each
    float vv[2];
#pragma unroll
    for (int r = 0; r < 2; r++) {
        int c = t + 256 * r;
        size_t idx = (size_t)row * HIDc + c;
        float x = 0.0f;
        for (int p = 0; p < nparts; p++) x += parts[(size_t)p * partStride + idx];
        if (bias) x += bias[c];
        if (res)  x += res[idx];
        vv[r] = x;
    }
    float s = vv[0] + vv[1];
    float qsum = vv[0] * vv[0] + vv[1] * vv[1];
#pragma unroll
    for (int o = 16; o > 0; o >>= 1) {
        s    += __shfl_down_sync(0xffffffffu, s, o);
        qsum += __shfl_down_sync(0xffffffffu, qsum, o);
    }
    __shared__ float ss[8], sq[8];
    __shared__ float s_mean, s_rstd;
    int warp = t >> 5, lane = t & 31;
    if (lane == 0) { ss[warp] = s; sq[warp] = qsum; }
    __syncthreads();
    if (t == 0) {
        float S = 0.0f, Q = 0.0f;
#pragma unroll
        for (int w = 0; w < 8; w++) { S += ss[w]; Q += sq[w]; }
        float mean = S * (1.0f / (float)HIDc);
        float var  = Q * (1.0f / (float)HIDc) - mean * mean;
        s_mean = mean;
        s_rstd = rsqrtf(var + EPS_LN);
    }
    __syncthreads();
#pragma unroll
    for (int r = 0; r < 2; r++) {
        int c = t + 256 * r;
        size_t idx = (size_t)row * HIDc + c;
        out[idx] = (vv[r] - s_mean) * s_rstd * g[c] + b[c];
    }
}

// ---------------- launcher ----------------------------------------------------
extern "C" void kernel_launch(void* const* d_in, const int* in_sizes, int n_in,
                              void* d_out, int out_size)
{
    (void)in_sizes; (void)n_in; (void)out_size;

    const int*   x     = (const int*)  d_in[0];
    const int*   pos   = (const int*)  d_in[1];
    const float* S     = (const float*)d_in[2];
    const float* Z     = (const float*)d_in[3];
    const float* emb   = (const float*)d_in[4];
    const float* Wq    = (const float*)d_in[5];
    const float* bq    = (const float*)d_in[6];
    const float* Wk    = (const float*)d_in[7];
    const float* bk    = (const float*)d_in[8];
    const float* Wv    = (const float*)d_in[9];
    const float* bv    = (const float*)d_in[10];
    const float* Wo    = (const float*)d_in[11];
    const float* bo    = (const float*)d_in[12];
    const float* W1    = (const float*)d_in[13];
    const float* b1    = (const float*)d_in[14];
    const float* W2    = (const float*)d_in[15];
    const float* b2    = (const float*)d_in[16];
    const float* ln1_g = (const float*)d_in[17];
    const float* ln1_b = (const float*)d_in[18];
    const float* ln2_g = (const float*)d_in[19];
    const float* ln2_b = (const float*)d_in[20];
    const float* lnf_g = (const float*)d_in[21];
    const float* lnf_b = (const float*)d_in[22];

    float* h_buf;  cudaGetSymbolAddress((void**)&h_buf,  g_h);
    float* a_buf;  cudaGetSymbolAddress((void**)&a_buf,  g_attn);
    float* ff_buf; cudaGetSymbolAddress((void**)&ff_buf, g_ff);
    float* p_buf;  cudaGetSymbolAddress((void**)&p_buf,  g_part);
    float* qkvp;   cudaGetSymbolAddress((void**)&qkvp,   g_qkvp);

    const size_t SZ = (size_t)Bc * Hc * Dc * Dc;  // 8388608 per layer
    const size_t ZZ = (size_t)Bc * Hc * Dc;       // 131072  per layer
    const size_t MN = (size_t)MNc;                // 131072

    float* out   = (float*)d_out;
    float* out_h = out;                           // [B,HID]
    float* out_S = out + MN;                      // [L,B,H,D,D]
    float* out_Z = out + MN + (size_t)Lc * SZ;    // [L,B,H,D]

    // embedding + positional encoding
    embed_kernel<<<(Bc * HIDc) / 256, 256>>>(x, pos, emb, h_buf);

    for (int l = 0; l < Lc; l++) {
        const float* Wq_l = Wq + (size_t)l * HIDc * HIDc;
        const float* Wk_l = Wk + (size_t)l * HIDc * HIDc;
        const float* Wv_l = Wv + (size_t)l * HIDc * HIDc;
        const float* Wo_l = Wo + (size_t)l * HIDc * HIDc;
        const float* W1_l = W1 + (size_t)l * HIDc * FFc;
        const float* W2_l = W2 + (size_t)l * FFc * HIDc;

        // QKV: split-K=2 per matrix -> 192 blocks, raw partials
        gemm_qkv_kernel<<<dim3(HIDc / 64, Bc / 64, 6), 256>>>(
            h_buf, Wq_l, Wk_l, Wv_l, qkvp);

        // fused QKV-reduce + bias + elu(+1) + S/Z update + attention
        attn_state_kernel<<<Bc * Hc, 256>>>(
            S + (size_t)l * SZ, Z + (size_t)l * ZZ,
            qkvp, bq + l * HIDc, bk + l * HIDc, bv + l * HIDc,
            out_S + (size_t)l * SZ, out_Z + (size_t)l * ZZ, a_buf);

        // O projection, split-K=8 into partials (256 blocks)
        gemm_kernel<<<dim3(HIDc / 64, Bc / 64, 8), 256>>>(
            a_buf, Wo_l, nullptr, p_buf, Bc, HIDc, HIDc, 0);

        // h = LN1(h + attn@Wo + bo)
        ln_kernel<<<Bc, 256>>>(p_buf, 8, (int)MN, bo + l * HIDc, h_buf,
                               ln1_g + l * HIDc, ln1_b + l * HIDc, h_buf);

        // FF1 with fused ReLU (128 blocks)
        gemm_kernel<<<dim3(FFc / 64, Bc / 64, 1), 256>>>(
            h_buf, W1_l, b1 + l * FFc, ff_buf, Bc, FFc, HIDc, 2);

        // FF2, split-K=8 into partials (256 blocks)
        gemm_kernel<<<dim3(HIDc / 64, Bc / 64, 8), 256>>>(
            ff_buf, W2_l, nullptr, p_buf, Bc, HIDc, FFc, 0);

        // h = LN2(h + ff)
        ln_kernel<<<Bc, 256>>>(p_buf, 8, (int)MN, b2 + l * HIDc, h_buf,
                               ln2_g + l * HIDc, ln2_b + l * HIDc, h_buf);
    }

    // final LayerNorm straight into d_out
    ln_kernel<<<Bc, 256>>>(h_buf, 1, 0, nullptr, nullptr, lnf_g, lnf_b, out_h);
}